// round 1
// baseline (speedup 1.0000x reference)
#include <cuda_runtime.h>

// CalculateSLayer: a = adj.sum(axis=2)  (4096x4096)
//   s_in[j,d]  = sum_i a[i,j] * s[i,d]   (= a^T @ s)
//   s_out[i,d] = sum_j a[i,j] * s[j,d]   (= a  @ s)
// Output layout: [ s_in (N*D) | s_out (N*D) ]  fp32.
//
// Single pass over adj: each CTA owns a BI x BJ tile of `a`, computes
//   - a partial of s_out for its BI rows (K-split over the 16 column tiles)
//   - the COMPLETE per-row-stripe partial of s_in for its BJ columns
// Partials go to __device__ scratch; a second kernel reduces the splits.

#define NN   4096
#define DD   70
#define DP   72        // padded D (zero pad), keeps thread tiling uniform
#define BI   128       // rows of a per CTA
#define BJ   256       // cols of a per CTA
#define CJ   64        // column chunk staged in smem
#define TI_TILES (NN / BI)   // 32  -> splits for s_in reduction
#define TJ_TILES (NN / BJ)   // 16  -> splits for s_out reduction
#define NTHREADS 256

// Split-K scratch (written fully each launch; deterministic).
__device__ float g_out_part[TJ_TILES][NN][DP];  // ~18.9 MB
__device__ float g_in_part [TI_TILES][NN][DP];  // ~37.7 MB

// smem layout (dynamic): a_shT[CJ][BI+1] | s_rows[BI][DP] | s_cols[CJ][DP]
#define SMEM_A_ELEMS   (CJ * (BI + 1))
#define SMEM_SR_ELEMS  (BI * DP)
#define SMEM_SC_ELEMS  (CJ * DP)
#define SMEM_BYTES     ((SMEM_A_ELEMS + SMEM_SR_ELEMS + SMEM_SC_ELEMS) * 4)

__global__ __launch_bounds__(NTHREADS, 2)
void slayer_main(const float* __restrict__ adj, const float* __restrict__ s)
{
    extern __shared__ float sm[];
    float* a_shT  = sm;                                // [CJ][BI+1], a^T chunk
    float* s_rows = a_shT + SMEM_A_ELEMS;              // [BI][DP]
    float* s_cols = s_rows + SMEM_SR_ELEMS;            // [CJ][DP]

    const int ti  = blockIdx.y;        // 0..31  (row tile)
    const int tj  = blockIdx.x;        // 0..15  (col tile)
    const int tid = threadIdx.x;

    // ---- stage s rows for this CTA's i-range (used by the a^T GEMM) ----
    for (int idx = tid; idx < BI * DP; idx += NTHREADS) {
        const int i = idx / DP, d = idx - i * DP;
        s_rows[idx] = (d < DD) ? s[(size_t)(ti * BI + i) * DD + d] : 0.f;
    }

    // G1 (s_out) thread tile: 32 x 8 threads, each owns 4 rows x 9 d
    const int ii  = tid >> 3;          // 0..31 -> i = ii*4 .. +4
    const int dg1 = tid & 7;           // 0..7  -> d = dg1*9 .. +9
    float acc[4][9];
#pragma unroll
    for (int r = 0; r < 4; r++)
#pragma unroll
        for (int t = 0; t < 9; t++) acc[r][t] = 0.f;

    // G2 (s_in) thread tile: 64 x 4 threads, each owns 1 col x 18 d
    const int jl  = tid & 63;          // 0..63 local j
    const int dg2 = tid >> 6;          // 0..3  -> d = dg2*18 .. +18

    const float2* __restrict__ adj2 = (const float2*)adj;  // (adj[..,0], adj[..,1])

    for (int jc = 0; jc < BJ / CJ; jc++) {
        __syncthreads();   // previous chunk's compute done before overwrite

        // ---- load a chunk (channel-summed) transposed into smem ----
        // consecutive tids -> consecutive j: global reads are contiguous float2
        for (int idx = tid; idx < BI * CJ; idx += NTHREADS) {
            const int i = idx >> 6;            // idx / CJ
            const int j = idx & (CJ - 1);
            const float2 v = adj2[(size_t)(ti * BI + i) * NN + (tj * BJ + jc * CJ + j)];
            a_shT[j * (BI + 1) + i] = v.x + v.y;   // stride 129 floats: conflict-free
        }
        // ---- stage s for this chunk's j-range ----
        for (int idx = tid; idx < CJ * DP; idx += NTHREADS) {
            const int j = idx / DP, d = idx - j * DP;
            s_cols[idx] = (d < DD)
                ? s[(size_t)(tj * BJ + jc * CJ + j) * DD + d] : 0.f;
        }
        __syncthreads();

        // ---- G1: acc(BI x DP) += a_chunk @ s_cols  (reduce over k=j) ----
#pragma unroll 4
        for (int k = 0; k < CJ; k++) {
            float av[4], sv[9];
#pragma unroll
            for (int r = 0; r < 4; r++) av[r] = a_shT[k * (BI + 1) + ii * 4 + r];
#pragma unroll
            for (int t = 0; t < 9; t++) sv[t] = s_cols[k * DP + dg1 * 9 + t];
#pragma unroll
            for (int r = 0; r < 4; r++)
#pragma unroll
                for (int t = 0; t < 9; t++)
                    acc[r][t] = fmaf(av[r], sv[t], acc[r][t]);
        }

        // ---- G2: s_in chunk partial = a_chunk^T @ s_rows (reduce over i) ----
        float accin[18];
#pragma unroll
        for (int t = 0; t < 18; t++) accin[t] = 0.f;
#pragma unroll 2
        for (int i = 0; i < BI; i++) {
            const float av = a_shT[jl * (BI + 1) + i];   // lanes: distinct banks
#pragma unroll
            for (int t = 0; t < 18; t++)
                accin[t] = fmaf(av, s_rows[i * DP + dg2 * 18 + t], accin[t]);
        }
        {   // complete over this CTA's i-range -> write straight to scratch
            const int jg = tj * BJ + jc * CJ + jl;
            float* dst = &g_in_part[ti][jg][dg2 * 18];
#pragma unroll
            for (int t = 0; t < 18; t++) dst[t] = accin[t];
        }
    }

    // ---- write s_out partial for this column split ----
#pragma unroll
    for (int r = 0; r < 4; r++) {
        const int ig = ti * BI + ii * 4 + r;
        float* dst = &g_out_part[tj][ig][dg1 * 9];
#pragma unroll
        for (int t = 0; t < 9; t++) dst[t] = acc[r][t];
    }
}

__global__ void slayer_reduce(float* __restrict__ out)
{
    const int idx = blockIdx.x * 256 + threadIdx.x;
    if (idx < NN * DD) {                       // s_in at offset 0
        const int j = idx / DD, d = idx - j * DD;
        float v = 0.f;
#pragma unroll
        for (int sp = 0; sp < TI_TILES; sp++) v += g_in_part[sp][j][d];
        out[idx] = v;
    } else if (idx < 2 * NN * DD) {            // s_out at offset N*D
        const int t = idx - NN * DD;
        const int i = t / DD, d = t - i * DD;
        float v = 0.f;
#pragma unroll
        for (int sp = 0; sp < TJ_TILES; sp++) v += g_out_part[sp][i][d];
        out[idx] = v;
    }
}

extern "C" void kernel_launch(void* const* d_in, const int* in_sizes, int n_in,
                              void* d_out, int out_size)
{
    const float* adj = (const float*)d_in[0];   // (4096, 4096, 2) fp32
    const float* s   = (const float*)d_in[1];   // (4096, 70) fp32
    float* out = (float*)d_out;                 // 2*4096*70 fp32: [s_in | s_out]

    cudaFuncSetAttribute(slayer_main,
                         cudaFuncAttributeMaxDynamicSharedMemorySize, SMEM_BYTES);

    dim3 grid(TJ_TILES, TI_TILES);              // (16, 32) = 512 CTAs
    slayer_main<<<grid, NTHREADS, SMEM_BYTES>>>(adj, s);

    const int total = 2 * NN * DD;
    slayer_reduce<<<(total + 255) / 256, 256>>>(out);
}

// round 4
// speedup vs baseline: 1.1777x; 1.1777x over previous
#include <cuda_runtime.h>

// CalculateSLayer: a = adj.sum(axis=2)  (4096x4096)
//   s_in[j,d]  = sum_i a[i,j] * s[i,d]   (= a^T @ s)
//   s_out[i,d] = sum_j a[i,j] * s[j,d]   (= a  @ s)
// Output: [ s_in (N*D) | s_out (N*D) ]  fp32.
//
// Packed-f32x2 (FFMA2) version: all inner-loop math is fma.rn.f32x2, smem
// reads are LDS.64/LDS.128. Single pass over adj; split-K partials in
// __device__ scratch; float2-vectorized reduce kernel.

#define NN   4096
#define DD   70
#define DP   80        // padded D (zero pad) -> 40 f32x2 pairs
#define NP   40        // DP/2 pairs
#define BI   128       // rows of a per CTA
#define BJ   256       // cols of a per CTA
#define CJ   64        // column chunk staged in smem
#define STR  132       // a_shT row stride (floats): even + 16B-aligned rows
#define TI_TILES (NN / BI)   // 32 splits for s_in
#define TJ_TILES (NN / BJ)   // 16 splits for s_out
#define NTHREADS 256

typedef unsigned long long u64;

// Split-K scratch (fully rewritten each launch; deterministic).
__device__ float g_out_part[TJ_TILES][NN][DP];  // ~21 MB
__device__ float g_in_part [TI_TILES][NN][DP];  // ~42 MB

// smem: a_shT[CJ][STR] | s_rows[BI][DP] | s_cols[CJ][DP]
#define SMEM_A_ELEMS   (CJ * STR)        // 8448
#define SMEM_SR_ELEMS  (BI * DP)         // 10240
#define SMEM_SC_ELEMS  (CJ * DP)         // 5120
#define SMEM_BYTES     ((SMEM_A_ELEMS + SMEM_SR_ELEMS + SMEM_SC_ELEMS) * 4)

__device__ __forceinline__ u64 dup2(float x) {
    u64 r;
    asm("mov.b64 %0, {%1, %1};" : "=l"(r) : "f"(x));
    return r;
}
__device__ __forceinline__ void fma2(u64& d, u64 a, u64 b) {
    asm("fma.rn.f32x2 %0, %1, %2, %0;" : "+l"(d) : "l"(a), "l"(b));
}

__global__ __launch_bounds__(NTHREADS, 2)
void slayer_main(const float* __restrict__ adj, const float* __restrict__ s)
{
    extern __shared__ float sm[];
    float* a_shT  = sm;                        // [CJ][STR], a^T chunk
    float* s_rows = a_shT + SMEM_A_ELEMS;      // [BI][DP]
    float* s_cols = s_rows + SMEM_SR_ELEMS;    // [CJ][DP]

    const float4* a4   = reinterpret_cast<const float4*>(a_shT);   // stride 33
    const u64*    sr64 = reinterpret_cast<const u64*>(s_rows);
    const u64*    sc64 = reinterpret_cast<const u64*>(s_cols);

    const int ti  = blockIdx.y;        // 0..31 (row tile)
    const int tj  = blockIdx.x;        // 0..15 (col tile)
    const int tid = threadIdx.x;

    // ---- stage s rows for this CTA's i-range (used by G2 / s_in) ----
    for (int idx = tid; idx < BI * DP; idx += NTHREADS) {
        const int i = idx / DP, d = idx - i * DP;
        s_rows[idx] = (d < DD) ? s[(size_t)(ti * BI + i) * DD + d] : 0.f;
    }

    // G1 (s_out): 32 i-threads x 8 d-groups; thread owns 4 rows x 5 pairs
    const int it  = tid >> 3;          // 0..31 -> rows it*4 .. +3
    const int dg1 = tid & 7;           // 0..7  -> pairs dg1*5 .. +4
    u64 acc[4][5];
#pragma unroll
    for (int r = 0; r < 4; r++)
#pragma unroll
        for (int p = 0; p < 5; p++) acc[r][p] = 0ull;

    // G2 (s_in): 32 j-threads x 8 d-groups; thread owns 2 cols x 5 pairs
    const int jt  = tid >> 3;          // 0..31 -> cols jt*2, jt*2+1
    const int dg2 = tid & 7;           // 0..7  -> pairs dg2*5 .. +4

    const float2* __restrict__ adj2 = (const float2*)adj;  // (ch0, ch1)

    for (int jc = 0; jc < BJ / CJ; jc++) {
        __syncthreads();   // previous chunk fully consumed

        // ---- load a chunk, channel-summed, transposed into smem ----
        for (int idx = tid; idx < BI * CJ; idx += NTHREADS) {
            const int i = idx >> 6;            // idx / CJ
            const int j = idx & (CJ - 1);
            const float2 v = adj2[(size_t)(ti * BI + i) * NN + (tj * BJ + jc * CJ + j)];
            a_shT[j * STR + i] = v.x + v.y;
        }
        // ---- stage s for this chunk's j-range ----
        for (int idx = tid; idx < CJ * DP; idx += NTHREADS) {
            const int j = idx / DP, d = idx - j * DP;
            s_cols[idx] = (d < DD)
                ? s[(size_t)(tj * BJ + jc * CJ + j) * DD + d] : 0.f;
        }
        __syncthreads();

        // ---- G1: acc += a_chunk @ s_cols (reduce over k=j_local) ----
#pragma unroll 4
        for (int k = 0; k < CJ; k++) {
            const float4 av = a4[k * (STR / 4) + it];      // LDS.128, 4 rows
            const u64 b0 = dup2(av.x), b1 = dup2(av.y);
            const u64 b2 = dup2(av.z), b3 = dup2(av.w);
            const u64* sp = sc64 + k * NP + dg1 * 5;
#pragma unroll
            for (int p = 0; p < 5; p++) {
                const u64 sv = sp[p];                      // LDS.64
                fma2(acc[0][p], b0, sv);
                fma2(acc[1][p], b1, sv);
                fma2(acc[2][p], b2, sv);
                fma2(acc[3][p], b3, sv);
            }
        }

        // ---- G2: s_in chunk partial = a_chunk^T @ s_rows (reduce over i,
        //      two i per iteration: a-values come in as LDS.64 pairs) ----
        u64 accin[2][5];
#pragma unroll
        for (int c = 0; c < 2; c++)
#pragma unroll
            for (int p = 0; p < 5; p++) accin[c][p] = 0ull;

#pragma unroll 2
        for (int i = 0; i < BI; i += 2) {
            const float2 a0 = *reinterpret_cast<const float2*>(
                &a_shT[(jt * 2 + 0) * STR + i]);           // LDS.64 (i even, STR even)
            const float2 a1 = *reinterpret_cast<const float2*>(
                &a_shT[(jt * 2 + 1) * STR + i]);
            const u64 b00 = dup2(a0.x), b01 = dup2(a0.y);
            const u64 b10 = dup2(a1.x), b11 = dup2(a1.y);
            const u64* sp0 = sr64 + (i + 0) * NP + dg2 * 5;
            const u64* sp1 = sr64 + (i + 1) * NP + dg2 * 5;
#pragma unroll
            for (int p = 0; p < 5; p++) {
                const u64 sv0 = sp0[p];                    // LDS.64
                const u64 sv1 = sp1[p];
                fma2(accin[0][p], b00, sv0);
                fma2(accin[1][p], b10, sv0);
                fma2(accin[0][p], b01, sv1);
                fma2(accin[1][p], b11, sv1);
            }
        }
        // complete over this CTA's i-range -> straight to scratch (STG.64)
#pragma unroll
        for (int c = 0; c < 2; c++) {
            const int jg = tj * BJ + jc * CJ + jt * 2 + c;
            u64* dst = reinterpret_cast<u64*>(&g_in_part[ti][jg][dg2 * 10]);
#pragma unroll
            for (int p = 0; p < 5; p++) dst[p] = accin[c][p];
        }
    }

    // ---- write s_out partial for this column split ----
#pragma unroll
    for (int r = 0; r < 4; r++) {
        const int ig = ti * BI + it * 4 + r;
        u64* dst = reinterpret_cast<u64*>(&g_out_part[tj][ig][dg1 * 10]);
#pragma unroll
        for (int p = 0; p < 5; p++) dst[p] = acc[r][p];
    }
}

// Reduce splits. Each thread owns one float2 (pair of d's); DD=70 -> 35 pairs.
#define HALFP (NN * 35)

__global__ void slayer_reduce(float* __restrict__ out)
{
    const int idx = blockIdx.x * 256 + threadIdx.x;
    if (idx < HALFP) {                          // s_in at offset 0
        const int j = idx / 35, dp = idx - j * 35;
        float2 v = make_float2(0.f, 0.f);
#pragma unroll
        for (int sp = 0; sp < TI_TILES; sp++) {
            const float2 t = *reinterpret_cast<const float2*>(&g_in_part[sp][j][dp * 2]);
            v.x += t.x; v.y += t.y;
        }
        reinterpret_cast<float2*>(out)[(size_t)j * 35 + dp] = v;
    } else if (idx < 2 * HALFP) {               // s_out at offset N*D
        const int t0 = idx - HALFP;
        const int i = t0 / 35, dp = t0 - i * 35;
        float2 v = make_float2(0.f, 0.f);
#pragma unroll
        for (int sp = 0; sp < TJ_TILES; sp++) {
            const float2 t = *reinterpret_cast<const float2*>(&g_out_part[sp][i][dp * 2]);
            v.x += t.x; v.y += t.y;
        }
        reinterpret_cast<float2*>(out + (size_t)NN * DD)[(size_t)i * 35 + dp] = v;
    }
}

extern "C" void kernel_launch(void* const* d_in, const int* in_sizes, int n_in,
                              void* d_out, int out_size)
{
    const float* adj = (const float*)d_in[0];   // (4096, 4096, 2) fp32
    const float* s   = (const float*)d_in[1];   // (4096, 70) fp32
    float* out = (float*)d_out;                 // [s_in | s_out], 2*4096*70 fp32

    cudaFuncSetAttribute(slayer_main,
                         cudaFuncAttributeMaxDynamicSharedMemorySize, SMEM_BYTES);

    dim3 grid(TJ_TILES, TI_TILES);              // (16, 32) = 512 CTAs
    slayer_main<<<grid, NTHREADS, SMEM_BYTES>>>(adj, s);

    const int totalp = 2 * HALFP;
    slayer_reduce<<<(totalp + 255) / 256, 256>>>(out);
}